// round 1
// baseline (speedup 1.0000x reference)
#include <cuda_runtime.h>

// Quanvolutional layer, analytically collapsed.
//
// Heisenberg-picture reduction of the 9-qubit circuit (RY(pi*x) encoding,
// RX(w) layer, CNOT ring) gives, with z_q = cos(w_q)*cos(pi*x_q):
//   <Z0> = z1*z2*...*z8
//   <Z1> = z0*z1
//   <Z2> = z0*z1*z2
//   <Z3> = z0*z1*z2*z3
// summed over the 3 input channels. Output is the raw-memory reshape of
// [Hout, Hout, F] -> [1, F, Hout, Hout], i.e. out[(i*Hout + j)*4 + f].

#define KH 96
#define HOUT 94

__global__ __launch_bounds__(256)
void quanv_kernel(const float* __restrict__ x,
                  const float* __restrict__ w,
                  float* __restrict__ out) {
    int idx = blockIdx.x * blockDim.x + threadIdx.x;
    if (idx >= HOUT * HOUT) return;
    int i = idx / HOUT;
    int j = idx - i * HOUT;

    // cos of the 9 RX weights (broadcast loads, L1-resident)
    float cw[9];
#pragma unroll
    for (int q = 0; q < 9; q++) cw[q] = cosf(w[q]);

    float ev0 = 0.f, ev1 = 0.f, ev2 = 0.f, ev3 = 0.f;

#pragma unroll
    for (int c = 0; c < 3; c++) {
        const float* xc = x + c * KH * KH + i * KH + j;
        float z[9];
#pragma unroll
        for (int r = 0; r < 3; r++) {
#pragma unroll
            for (int s = 0; s < 3; s++) {
                z[r * 3 + s] = cw[r * 3 + s] * cospif(__ldg(xc + r * KH + s));
            }
        }
        float p01   = z[0] * z[1];
        float p012  = p01 * z[2];
        float p0123 = p012 * z[3];
        ev1 += p01;
        ev2 += p012;
        ev3 += p0123;
        float a = z[1] * z[2];
        float b = z[3] * z[4];
        float c2 = z[5] * z[6];
        float d = z[7] * z[8];
        ev0 += (a * b) * (c2 * d);
    }

    reinterpret_cast<float4*>(out)[idx] = make_float4(ev0, ev1, ev2, ev3);
}

extern "C" void kernel_launch(void* const* d_in, const int* in_sizes, int n_in,
                              void* d_out, int out_size) {
    const float* x = (const float*)d_in[0];   // [1,3,96,96]
    const float* w = (const float*)d_in[1];   // [1,9]
    float* out = (float*)d_out;               // [1,4,94,94] (reinterpret of [94,94,4])

    const int total = HOUT * HOUT;            // 8836 pixels
    const int threads = 256;
    const int blocks = (total + threads - 1) / threads;
    quanv_kernel<<<blocks, threads>>>(x, w, out);
}

// round 2
// speedup vs baseline: 1.2977x; 1.2977x over previous
#include <cuda_runtime.h>
#include <math_constants.h>

// Quanvolutional layer, analytically collapsed (Heisenberg picture):
// with z_q = cos(w_q) * cos(pi * x_q):
//   <Z0> = z1*...*z8,  <Z1> = z0*z1,  <Z2> = z0*z1*z2,  <Z3> = z0*z1*z2*z3
// summed over 3 channels. Output = raw reshape [94,94,4] -> out[(i*94+j)*4+f].
//
// R1: shared-memory tiling dedups the per-element cosine (each input element
// is reused by up to 9 patches), and __cosf replaces the slow polynomial
// cospif. cos(w) computed once per block.

#define KH 96
#define HOUT 94
#define TX 32
#define TY 8
// input tile: (TX+2) x (TY+2) per channel
#define GW 34
#define GH 10
#define GSTRIDE 36   // padded row stride (floats)

__global__ __launch_bounds__(TX * TY)
void quanv_kernel(const float* __restrict__ x,
                  const float* __restrict__ w,
                  float* __restrict__ out) {
    __shared__ float cw[9];
    __shared__ float g[3][GH][GSTRIDE];

    const int tx = threadIdx.x;
    const int ty = threadIdx.y;
    const int tid = ty * TX + tx;
    const int i0 = blockIdx.y * TY;   // output-row origin of tile
    const int j0 = blockIdx.x * TX;   // output-col origin of tile

    if (tid < 9) cw[tid] = cosf(w[tid]);

    // Cooperative load + transform: g = cos(pi * x) for the input tile.
    // 3 * 10 * 34 = 1020 elements over 256 threads.
    for (int k = tid; k < 3 * GH * GW; k += TX * TY) {
        int c   = k / (GH * GW);
        int rem = k - c * (GH * GW);
        int r   = rem / GW;
        int col = rem - r * GW;
        int gi = i0 + r;
        int gj = j0 + col;
        float v = 0.f;
        if (gi < KH && gj < KH)
            v = __cosf(CUDART_PI_F * x[c * KH * KH + gi * KH + gj]);
        g[c][r][col] = v;
    }
    __syncthreads();

    const int i = i0 + ty;
    const int j = j0 + tx;
    if (i >= HOUT || j >= HOUT) return;

    float ev0 = 0.f, ev1 = 0.f, ev2 = 0.f, ev3 = 0.f;

#pragma unroll
    for (int c = 0; c < 3; c++) {
        float z[9];
#pragma unroll
        for (int r = 0; r < 3; r++)
#pragma unroll
            for (int s = 0; s < 3; s++)
                z[r * 3 + s] = cw[r * 3 + s] * g[c][ty + r][tx + s];

        float p01   = z[0] * z[1];
        float p012  = p01 * z[2];
        float p0123 = p012 * z[3];
        ev1 += p01;
        ev2 += p012;
        ev3 += p0123;
        float a = z[1] * z[2];
        float b = z[3] * z[4];
        float d = z[5] * z[6];
        float e = z[7] * z[8];
        ev0 += (a * b) * (d * e);
    }

    reinterpret_cast<float4*>(out)[i * HOUT + j] =
        make_float4(ev0, ev1, ev2, ev3);
}

extern "C" void kernel_launch(void* const* d_in, const int* in_sizes, int n_in,
                              void* d_out, int out_size) {
    const float* x = (const float*)d_in[0];   // [1,3,96,96]
    const float* w = (const float*)d_in[1];   // [1,9]
    float* out = (float*)d_out;               // [1,4,94,94]

    dim3 block(TX, TY);
    dim3 grid((HOUT + TX - 1) / TX, (HOUT + TY - 1) / TY);  // 3 x 12 = 36 blocks
    quanv_kernel<<<grid, block>>>(x, w, out);
}

// round 3
// speedup vs baseline: 1.4235x; 1.0969x over previous
#include <cuda_runtime.h>
#include <math_constants.h>

// Quanvolutional layer, analytically collapsed (Heisenberg picture):
// with z_q = cos(w_q) * cos(pi * x_q):
//   <Z0> = z1*...*z8,  <Z1> = z0*z1,  <Z2> = z0*z1*z2,  <Z3> = z0*z1*z2*z3
// summed over 3 channels. Output = raw reshape [94,94,4] -> out[(i*94+j)*4+f].
//
// R2: latency-floor attack. No smem, no barrier — the STS/BAR/LDS round-trip
// was on the critical path. 27 independent LDGs per thread (MLP=27) overlap
// with 27 MUFU __cosf. 70 blocks x 128 threads spreads across half the chip.

#define KH 96
#define HOUT 94

__global__ __launch_bounds__(128)
void quanv_kernel(const float* __restrict__ x,
                  const float* __restrict__ w,
                  float* __restrict__ out) {
    int idx = blockIdx.x * blockDim.x + threadIdx.x;
    if (idx >= HOUT * HOUT) return;
    int i = idx / HOUT;
    int j = idx - i * HOUT;

    // 9 weight cosines (broadcast loads, independent MUFUs)
    float cw[9];
#pragma unroll
    for (int q = 0; q < 9; q++) cw[q] = __cosf(__ldg(w + q));

    // Load all 27 inputs up-front (independent -> high MLP)
    float v[3][9];
#pragma unroll
    for (int c = 0; c < 3; c++) {
        const float* xc = x + c * KH * KH + i * KH + j;
#pragma unroll
        for (int r = 0; r < 3; r++)
#pragma unroll
            for (int s = 0; s < 3; s++)
                v[c][r * 3 + s] = __ldg(xc + r * KH + s);
    }

    float ev0 = 0.f, ev1 = 0.f, ev2 = 0.f, ev3 = 0.f;

#pragma unroll
    for (int c = 0; c < 3; c++) {
        float z[9];
#pragma unroll
        for (int q = 0; q < 9; q++)
            z[q] = cw[q] * __cosf(CUDART_PI_F * v[c][q]);

        float p01   = z[0] * z[1];
        float p012  = p01 * z[2];
        float p0123 = p012 * z[3];
        ev1 += p01;
        ev2 += p012;
        ev3 += p0123;
        float a = z[1] * z[2];
        float b = z[3] * z[4];
        float d = z[5] * z[6];
        float e = z[7] * z[8];
        ev0 += (a * b) * (d * e);
    }

    reinterpret_cast<float4*>(out)[idx] = make_float4(ev0, ev1, ev2, ev3);
}

extern "C" void kernel_launch(void* const* d_in, const int* in_sizes, int n_in,
                              void* d_out, int out_size) {
    const float* x = (const float*)d_in[0];   // [1,3,96,96]
    const float* w = (const float*)d_in[1];   // [1,9]
    float* out = (float*)d_out;               // [1,4,94,94]

    const int total = HOUT * HOUT;            // 8836
    const int threads = 128;
    const int blocks = (total + threads - 1) / threads;  // 70 blocks
    quanv_kernel<<<blocks, threads>>>(x, w, out);
}